// round 8
// baseline (speedup 1.0000x reference)
#include <cuda_runtime.h>

// Point_Transformer fused kernel for sm_100a — round 6 design (3rd submit; broker flaky).
// Half-warp per point, 4 output channels per lane. Broadcast row loads shared
// across the two half-warps (bank-offset buffers); weights as one float4/lane.
// x3 matvec eliminated via gating algebra (y/pg); Ww2 transposed.

#define NN 8192
#define NKK 10
#define WARPS 16
#define THREADS 512
#define GRID 148
#define NTILE 2048      // 65536 points / 32 per block-tile

typedef unsigned long long ull;

__device__ __forceinline__ ull pk2(float lo, float hi) {
    ull r; asm("mov.b64 %0,{%1,%2};" : "=l"(r) : "f"(lo), "f"(hi)); return r;
}
__device__ __forceinline__ void upk(ull v, float& lo, float& hi) {
    asm("mov.b64 {%0,%1},%2;" : "=f"(lo), "=f"(hi) : "l"(v));
}
__device__ __forceinline__ void f2(ull& d, ull a, ull b) {
    asm("fma.rn.f32x2 %0,%1,%2,%0;" : "+l"(d) : "l"(a), "l"(b));
}

struct __align__(16) Smem {
    float W0t[4096];            // [cin][cout]
    float W1t[4096];
    float W2t[4096];
    float W3t[4096];
    float Wot[4096];
    float Ww1[5120];            // [8][640]
    float Ww2t[640];            // [8][80]  (transposed: conflict-free logits)
    float Mv[64];               // Wp2 @ relu(Wp1)
    float b0[64], b1[64], b2[64], b3[64], bo[64];
    float bw2[80];
    float buf[WARPS][2][772];   // per point (772 pad => bank-offset between points)
    float pbuf[WARPS][2][16];   // ptsn
    float wvb[WARPS][2][100];   // softmax weights, rows g*12 (100 pad => bank offset)
    float stg[64 * 34];         // output staging
};

__global__ void __launch_bounds__(THREADS, 1)
pt_kernel(const float* __restrict__ gF,   // sm_feats (B,64,N,K)
          const float* __restrict__ gC,   // cent_pts (B,N,3)
          const float* __restrict__ gP,   // sm_pts   (B,3,N,K)
          const float* __restrict__ gW0, const float* __restrict__ gb0,
          const float* __restrict__ gW1, const float* __restrict__ gb1,
          const float* __restrict__ gW2, const float* __restrict__ gb2,
          const float* __restrict__ gW3, const float* __restrict__ gb3,
          const float* __restrict__ gWp1, const float* __restrict__ gWp2,
          const float* __restrict__ gWw1, const float* __restrict__ gWw2,
          const float* __restrict__ gbw2,
          const float* __restrict__ gWo, const float* __restrict__ gbo,
          float* __restrict__ gOut)
{
    extern __shared__ char raw[];
    Smem& S = *reinterpret_cast<Smem*>(raw);
    const int tid = threadIdx.x, lane = tid & 31, wid = tid >> 5;

    // ---- one-time weight staging ----
    for (int i = tid; i < 4096; i += THREADS) {
        int o = i >> 6, c = i & 63;
        int tix = c * 64 + o;
        S.W0t[tix] = gW0[i];
        S.W1t[tix] = gW1[i];
        S.W2t[tix] = gW2[i];
        S.W3t[tix] = gW3[i];
        S.Wot[tix] = gWo[i];
    }
    for (int i = tid; i < 5120; i += THREADS) S.Ww1[i] = gWw1[i];
    for (int i = tid; i < 640;  i += THREADS) {
        int j = i / 80, r = i - j * 80;
        S.Ww2t[j * 80 + r] = gWw2[r * 8 + j];
    }
    if (tid < 64) {
        float m = 0.f;
        #pragma unroll 8
        for (int c = 0; c < 64; ++c) m += gWp2[tid * 64 + c] * fmaxf(gWp1[c], 0.f);
        S.Mv[tid] = m;
        S.b0[tid] = gb0[tid]; S.b1[tid] = gb1[tid]; S.b2[tid] = gb2[tid];
        S.b3[tid] = gb3[tid]; S.bo[tid] = gbo[tid];
    }
    if (tid >= 64 && tid < 144) S.bw2[tid - 64] = gbw2[tid - 64];
    __syncthreads();

    const int q  = lane & 15;          // channel-quad index within half-warp
    const int pt = lane >> 4;          // which point this lane works on
    const int o0 = q * 4;              // channels [o0, o0+4)
    const int gbase = (q & 1) * 4;     // gate groups for these channels
    float* mybuf = S.buf[wid][pt];
    float* mywv  = S.wvb[wid][pt];
    const float* mypb = S.pbuf[wid][pt];

    for (int t = blockIdx.x; t < NTILE; t += GRID) {
        const int p0 = t * 32;
        const int b  = p0 >> 13;
        const int n0 = p0 & (NN - 1);
        const int n  = n0 + wid * 2;   // warp: points n (pt=0), n+1 (pt=1)

        // ---- feats load: 64 rows x 20 floats (both points interleaved in gmem) ----
        {
            const float* fp = gF + (size_t)b * (64 * NN * NKK) + (size_t)n * NKK;
            #pragma unroll
            for (int i = lane; i < 1280; i += 32) {
                int c = i / 20, r = i - c * 20, ip = r / 10, k = r - ip * 10;
                S.buf[wid][ip][c * 12 + k] = fp[(size_t)c * (NN * NKK) + r];
            }
        }
        // ---- ptsn: lanes 0-9 point0, lanes 16-25 point1 ----
        if ((lane & 15) < 10 && lane < 26) {
            int ip = lane >> 4, k = lane & 15;
            const float* cp = gC + ((size_t)b * NN + n + ip) * 3;
            const float* pp = gP + (size_t)b * (3 * NN * NKK) + (size_t)(n + ip) * NKK + k;
            float dx = cp[0] - pp[0];
            float dy = cp[1] - pp[NN * NKK];
            float dz = cp[2] - pp[2 * NN * NKK];
            S.pbuf[wid][ip][k] = dx * dx + dy * dy + dz * dz;
        }
        __syncwarp();

        // ================= Phase 1: xn = relu(W0 @ feats + b0) ==================
        ull xa[4][5];
        {
            float4 bb = *(const float4*)(S.b0 + o0);
            float bj[4] = {bb.x, bb.y, bb.z, bb.w};
            #pragma unroll
            for (int j = 0; j < 4; j++) {
                ull iv = pk2(bj[j], bj[j]);
                #pragma unroll
                for (int q5 = 0; q5 < 5; q5++) xa[j][q5] = iv;
            }
        }
        #pragma unroll 2
        for (int c = 0; c < 64; c++) {
            const float* row = mybuf + c * 12;
            float4 r0 = *(const float4*)(row);
            float4 r1 = *(const float4*)(row + 4);
            float2 r2 = *(const float2*)(row + 8);
            ull xp[5] = { pk2(r0.x, r0.y), pk2(r0.z, r0.w),
                          pk2(r1.x, r1.y), pk2(r1.z, r1.w), pk2(r2.x, r2.y) };
            float4 w = *(const float4*)(S.W0t + c * 64 + o0);
            ull ws[4] = { pk2(w.x, w.x), pk2(w.y, w.y), pk2(w.z, w.z), pk2(w.w, w.w) };
            #pragma unroll
            for (int j = 0; j < 4; j++)
                #pragma unroll
                for (int q5 = 0; q5 < 5; q5++) f2(xa[j][q5], ws[j], xp[q5]);
        }
        float xnv[4][10];
        #pragma unroll
        for (int j = 0; j < 4; j++) {
            #pragma unroll
            for (int q5 = 0; q5 < 5; q5++)
                upk(xa[j][q5], xnv[j][2 * q5], xnv[j][2 * q5 + 1]);
            #pragma unroll
            for (int k = 0; k < 10; k++) xnv[j][k] = fmaxf(xnv[j][k], 0.f);
        }
        float x0res[4] = { xnv[0][0], xnv[1][0], xnv[2][0], xnv[3][0] };
        __syncwarp();   // everyone done reading feats
        #pragma unroll
        for (int j = 0; j < 4; j++) {
            float* rw = mybuf + (o0 + j) * 12;
            *(float4*)(rw)     = make_float4(xnv[j][0], xnv[j][1], xnv[j][2], xnv[j][3]);
            *(float4*)(rw + 4) = make_float4(xnv[j][4], xnv[j][5], xnv[j][6], xnv[j][7]);
            *(float2*)(rw + 8) = make_float2(xnv[j][8], xnv[j][9]);
        }
        __syncwarp();

        // ================= Phase 2: x2 (all k) and x1 (k=0) =====================
        ull a2[4][5], a1p[2];
        {
            float4 bb2 = *(const float4*)(S.b2 + o0);
            float bj[4] = {bb2.x, bb2.y, bb2.z, bb2.w};
            #pragma unroll
            for (int j = 0; j < 4; j++) {
                ull iv = pk2(bj[j], bj[j]);
                #pragma unroll
                for (int q5 = 0; q5 < 5; q5++) a2[j][q5] = iv;
            }
            float4 bb1 = *(const float4*)(S.b1 + o0);
            a1p[0] = pk2(bb1.x, bb1.y);
            a1p[1] = pk2(bb1.z, bb1.w);
        }
        #pragma unroll 2
        for (int c = 0; c < 64; c++) {
            const float* row = mybuf + c * 12;
            float4 r0 = *(const float4*)(row);
            float4 r1 = *(const float4*)(row + 4);
            float2 r2 = *(const float2*)(row + 8);
            ull xp[5] = { pk2(r0.x, r0.y), pk2(r0.z, r0.w),
                          pk2(r1.x, r1.y), pk2(r1.z, r1.w), pk2(r2.x, r2.y) };
            float xk0 = r0.x;
            float4 w2 = *(const float4*)(S.W2t + c * 64 + o0);
            ull ws[4] = { pk2(w2.x, w2.x), pk2(w2.y, w2.y), pk2(w2.z, w2.z), pk2(w2.w, w2.w) };
            #pragma unroll
            for (int j = 0; j < 4; j++)
                #pragma unroll
                for (int q5 = 0; q5 < 5; q5++) f2(a2[j][q5], ws[j], xp[q5]);
            float4 w1 = *(const float4*)(S.W1t + c * 64 + o0);
            ull xs = pk2(xk0, xk0);
            f2(a1p[0], pk2(w1.x, w1.y), xs);
            f2(a1p[1], pk2(w1.z, w1.w), xs);
        }

        // ---- xf = x1 - x2 + ptsn*M  (flat j*10+k) ----
        float x1v[4];
        upk(a1p[0], x1v[0], x1v[1]);
        upk(a1p[1], x1v[2], x1v[3]);
        float4 mv4 = *(const float4*)(S.Mv + o0);
        float Mj[4] = {mv4.x, mv4.y, mv4.z, mv4.w};
        float pbv[10];
        {
            float2 p0v = *(const float2*)(mypb);
            float2 p1v = *(const float2*)(mypb + 2);
            float2 p2v = *(const float2*)(mypb + 4);
            float2 p3v = *(const float2*)(mypb + 6);
            float2 p4v = *(const float2*)(mypb + 8);
            pbv[0]=p0v.x; pbv[1]=p0v.y; pbv[2]=p1v.x; pbv[3]=p1v.y; pbv[4]=p2v.x;
            pbv[5]=p2v.y; pbv[6]=p3v.x; pbv[7]=p3v.y; pbv[8]=p4v.x; pbv[9]=p4v.y;
        }
        ull pbp[5] = { pk2(pbv[0],pbv[1]), pk2(pbv[2],pbv[3]), pk2(pbv[4],pbv[5]),
                       pk2(pbv[6],pbv[7]), pk2(pbv[8],pbv[9]) };
        float xff[40];
        #pragma unroll
        for (int j = 0; j < 4; j++)
            #pragma unroll
            for (int q5 = 0; q5 < 5; q5++) {
                float u0, u1;
                upk(a2[j][q5], u0, u1);
                xff[j * 10 + 2 * q5]     = x1v[j] - u0 + pbv[2 * q5] * Mj[j];
                xff[j * 10 + 2 * q5 + 1] = x1v[j] - u1 + pbv[2 * q5 + 1] * Mj[j];
            }
        // re-read own xn rows as packed k-pairs (needed for y after softmax)
        ull xnp[4][5];
        #pragma unroll
        for (int j = 0; j < 4; j++) {
            const float* rw = mybuf + (o0 + j) * 12;
            float4 r0 = *(const float4*)(rw);
            float4 r1 = *(const float4*)(rw + 4);
            float2 r2 = *(const float2*)(rw + 8);
            xnp[j][0] = pk2(r0.x, r0.y); xnp[j][1] = pk2(r0.z, r0.w);
            xnp[j][2] = pk2(r1.x, r1.y); xnp[j][3] = pk2(r1.z, r1.w);
            xnp[j][4] = pk2(r2.x, r2.y);
        }
        __syncwarp();   // all xn reads done before xfs overwrite
        {
            float* xb = mybuf + 40 * q;   // lane-contiguous 160B, aligned
            #pragma unroll
            for (int ii = 0; ii < 10; ii++)
                *(float4*)(xb + 4 * ii) =
                    make_float4(xff[4*ii], xff[4*ii+1], xff[4*ii+2], xff[4*ii+3]);
        }
        __syncwarp();

        // ================= h = relu(Ww1 @ xfs) =================
        float h[2][8];
        #pragma unroll
        for (int j = 0; j < 8; j++) { h[0][j] = 0.f; h[1][j] = 0.f; }
        #pragma unroll 4
        for (int tt = 0; tt < 20; tt++) {
            int m = lane + tt * 32;
            float fA = S.buf[wid][0][m], fB = S.buf[wid][1][m];
            #pragma unroll
            for (int j = 0; j < 8; j++) {
                float w = S.Ww1[j * 640 + m];
                h[0][j] += w * fA;
                h[1][j] += w * fB;
            }
        }
        #pragma unroll
        for (int ip = 0; ip < 2; ip++)
            #pragma unroll
            for (int j = 0; j < 8; j++) {
                float v = h[ip][j];
                v += __shfl_xor_sync(0xffffffffu, v, 16);
                v += __shfl_xor_sync(0xffffffffu, v, 8);
                v += __shfl_xor_sync(0xffffffffu, v, 4);
                v += __shfl_xor_sync(0xffffffffu, v, 2);
                v += __shfl_xor_sync(0xffffffffu, v, 1);
                h[ip][j] = fmaxf(v, 0.f);
            }
        // ---- logits (Ww2t conflict-free) ----
        #pragma unroll
        for (int ip = 0; ip < 2; ip++) {
            float* wv = S.wvb[wid][ip];
            #pragma unroll
            for (int r = lane; r < 80; r += 32) {
                float v = S.bw2[r];
                #pragma unroll
                for (int j = 0; j < 8; j++) v += S.Ww2t[j * 80 + r] * h[ip][j];
                int g = r / 10, k = r - g * 10;
                wv[g * 12 + k] = v;
            }
        }
        __syncwarp();
        // ---- softmax over k ----
        if ((lane & 15) < 8 && lane < 24) {
            int ip = lane >> 4, g = lane & 15;
            float* wr = S.wvb[wid][ip] + g * 12;
            float mx = wr[0];
            #pragma unroll
            for (int k = 1; k < 10; k++) mx = fmaxf(mx, wr[k]);
            float e[10]; float sum = 0.f;
            #pragma unroll
            for (int k = 0; k < 10; k++) { e[k] = __expf(wr[k] - mx); sum += e[k]; }
            float inv = 1.f / sum;
            #pragma unroll
            for (int k = 0; k < 10; k++) wr[k] = e[k] * inv;
        }
        __syncwarp();

        // ====== y[cin][g] = sum_k wv[g,k]*xn[cin,k]  and  pg = wv @ ptsn ======
        ull pga[4] = { pk2(0.f,0.f), pk2(0.f,0.f), pk2(0.f,0.f), pk2(0.f,0.f) };
        float yrow[4][8];
        #pragma unroll
        for (int g = 0; g < 8; g++) {
            const float* wr = mywv + g * 12;
            float4 wa = *(const float4*)(wr);
            float4 wb = *(const float4*)(wr + 4);
            float2 wc = *(const float2*)(wr + 8);
            ull wv5[5] = { pk2(wa.x,wa.y), pk2(wa.z,wa.w),
                           pk2(wb.x,wb.y), pk2(wb.z,wb.w), pk2(wc.x,wc.y) };
            #pragma unroll
            for (int j = 0; j < 4; j++) {
                ull acc = pk2(0.f, 0.f);
                #pragma unroll
                for (int q5 = 0; q5 < 5; q5++) f2(acc, wv5[q5], xnp[j][q5]);
                float lo, hi; upk(acc, lo, hi);
                yrow[j][g] = lo + hi;
            }
            int tg = g - gbase;
            if (tg >= 0 && tg < 4) {
                #pragma unroll
                for (int q5 = 0; q5 < 5; q5++) f2(pga[tg], wv5[q5], pbp[q5]);
            }
        }
        float pg[4];
        #pragma unroll
        for (int j = 0; j < 4; j++) { float lo, hi; upk(pga[j], lo, hi); pg[j] = lo + hi; }
        #pragma unroll
        for (int j = 0; j < 4; j++) {      // y rows stride 12 (overwrites xfs)
            float* yb = mybuf + (o0 + j) * 12;
            *(float4*)(yb)     = make_float4(yrow[j][0], yrow[j][1], yrow[j][2], yrow[j][3]);
            *(float4*)(yb + 4) = make_float4(yrow[j][4], yrow[j][5], yrow[j][6], yrow[j][7]);
        }
        __syncwarp();

        // ====== s[o] = sum_cin W3[o,cin]*y[cin,g(o)]; op = relu(s+b3+M*pg) ======
        ull sacc[2] = { pk2(0.f,0.f), pk2(0.f,0.f) };
        #pragma unroll 4
        for (int cin = 0; cin < 64; cin++) {
            float4 w  = *(const float4*)(S.W3t + cin * 64 + o0);
            float4 yv = *(const float4*)(mybuf + cin * 12 + gbase);
            f2(sacc[0], pk2(w.x, w.y), pk2(yv.x, yv.y));
            f2(sacc[1], pk2(w.z, w.w), pk2(yv.z, yv.w));
        }
        __syncwarp();   // all y reads complete before op overwrites rows 0-5
        {
            float s0, s1, s2, s3;
            upk(sacc[0], s0, s1);
            upk(sacc[1], s2, s3);
            float4 bb3 = *(const float4*)(S.b3 + o0);
            float4 mvb = *(const float4*)(S.Mv + o0);
            *(float4*)(mybuf + o0) = make_float4(
                fmaxf(s0 + bb3.x + mvb.x * pg[0], 0.f),
                fmaxf(s1 + bb3.y + mvb.y * pg[1], 0.f),
                fmaxf(s2 + bb3.z + mvb.z * pg[2], 0.f),
                fmaxf(s3 + bb3.w + mvb.w * pg[3], 0.f));
        }
        __syncwarp();

        // ================= final = Wout @ op + bout + x =================
        ull facc[2];
        {
            float4 bbo = *(const float4*)(S.bo + o0);
            facc[0] = pk2(bbo.x + x0res[0], bbo.y + x0res[1]);
            facc[1] = pk2(bbo.z + x0res[2], bbo.w + x0res[3]);
        }
        #pragma unroll 4
        for (int c = 0; c < 64; c++) {
            float4 w = *(const float4*)(S.Wot + c * 64 + o0);
            float ov = mybuf[c];
            ull os = pk2(ov, ov);
            f2(facc[0], pk2(w.x, w.y), os);
            f2(facc[1], pk2(w.z, w.w), os);
        }
        float fo[4];
        upk(facc[0], fo[0], fo[1]);
        upk(facc[1], fo[2], fo[3]);

        __syncthreads();                 // prior tile's staged stores fully consumed
        #pragma unroll
        for (int j = 0; j < 4; j++)
            S.stg[(o0 + j) * 34 + wid * 2 + pt] = fo[j];
        __syncthreads();
        {
            float* ob = gOut + (size_t)b * 64 * NN + n0;
            #pragma unroll
            for (int i = tid; i < 2048; i += THREADS) {
                int o = i >> 5, jj = i & 31;
                ob[(size_t)o * NN + jj] = S.stg[o * 34 + jj];
            }
        }
    }
}

extern "C" void kernel_launch(void* const* d_in, const int* in_sizes, int n_in,
                              void* d_out, int out_size) {
    (void)in_sizes; (void)n_in; (void)out_size;
    cudaFuncSetAttribute(pt_kernel, cudaFuncAttributeMaxDynamicSharedMemorySize,
                         (int)sizeof(Smem));
    pt_kernel<<<GRID, THREADS, sizeof(Smem)>>>(
        (const float*)d_in[0],  (const float*)d_in[1],  (const float*)d_in[2],
        (const float*)d_in[3],  (const float*)d_in[4],
        (const float*)d_in[5],  (const float*)d_in[6],
        (const float*)d_in[7],  (const float*)d_in[8],
        (const float*)d_in[9],  (const float*)d_in[10],
        (const float*)d_in[11], (const float*)d_in[12],
        (const float*)d_in[13], (const float*)d_in[14], (const float*)d_in[15],
        (const float*)d_in[16], (const float*)d_in[17],
        (float*)d_out);
}